// round 11
// baseline (speedup 1.0000x reference)
#include <cuda_runtime.h>
#include <cuda_bf16.h>
#include <cstdint>
#include <math.h>

// ======================= Problem constants =======================
static constexpr int KDIM     = 128;   // inner dim
static constexpr int NOUT     = 256;   // grid points + 1
static constexpr int NUM_GRID = 255;
static constexpr int M_TILE   = 32;    // rows per group-tile

// Padded smem row stride: 128 bf16 + 8 pad = 272 bytes -> conflict-free ldmatrix
static constexpr int ROW_BYTES = 272;
static constexpr int A_BUF_HALF = M_TILE * ROW_BYTES;       // 8704 (hi or lo)
static constexpr int A_BUF      = 2 * A_BUF_HALF;           // 17408 per group

// SMEM layout (byte offsets in dynamic smem)
static constexpr int SM_BHI  = 0;                           // 256 x 272 = 69632
static constexpr int SM_BLO  = SM_BHI + NOUT * ROW_BYTES;   // 69632
static constexpr int SM_A    = SM_BLO + NOUT * ROW_BYTES;   // 139264: 2 group bufs
static constexpr int SM_BIAS = SM_A + 2 * A_BUF;            // 174080, 256 fp32
static constexpr int SM_T    = SM_BIAS + NOUT * 4;          // 175104, 2x32 fp32
static constexpr int SM_PMAX = SM_T + 256;                  // 175360, 2x32x4 fp32
static constexpr int SM_PSUM = SM_PMAX + 1024;              // 176384
static constexpr int SM_PY   = SM_PSUM + 1024;              // 177408
static constexpr int SM_TOTAL = SM_PY + 1024;               // 178432 (< 227 KB)

static constexpr float LOG2E = 1.4426950408889634f;

// Pre-split weights in gmem, K-major [n][k], bf16 hi/lo (pre-scaled by log2e)
__device__ __align__(16) __nv_bfloat16 g_whi[NOUT * KDIM];
__device__ __align__(16) __nv_bfloat16 g_wlo[NOUT * KDIM];

// ======================= small helpers =======================
__device__ __forceinline__ uint32_t smem_to_u32(const void* p) {
    uint32_t a;
    asm("{ .reg .u64 t; cvta.to.shared.u64 t, %1; cvt.u32.u64 %0, t; }"
        : "=r"(a) : "l"(p));
    return a;
}

__device__ __forceinline__ void ldsm_x4(uint32_t (&r)[4], uint32_t addr) {
    asm volatile("ldmatrix.sync.aligned.m8n8.x4.shared.b16 {%0,%1,%2,%3}, [%4];"
        : "=r"(r[0]), "=r"(r[1]), "=r"(r[2]), "=r"(r[3]) : "r"(addr));
}

__device__ __forceinline__ void mma_bf16(float* d, const uint32_t (&a)[4],
                                         uint32_t b0, uint32_t b1) {
    asm volatile(
        "mma.sync.aligned.m16n8k16.row.col.f32.bf16.bf16.f32 "
        "{%0,%1,%2,%3},{%4,%5,%6,%7},{%8,%9},{%0,%1,%2,%3};"
        : "+f"(d[0]), "+f"(d[1]), "+f"(d[2]), "+f"(d[3])
        : "r"(a[0]), "r"(a[1]), "r"(a[2]), "r"(a[3]), "r"(b0), "r"(b1));
}

__device__ __forceinline__ uint32_t pack_bf16(__nv_bfloat16 a, __nv_bfloat16 b) {
    return (uint32_t)__bfloat16_as_ushort(a) | ((uint32_t)__bfloat16_as_ushort(b) << 16);
}

__device__ __forceinline__ float ex2f(float x) {
    float y;
    asm("ex2.approx.ftz.f32 %0, %1;" : "=f"(y) : "f"(x));
    return y;
}

// convert one float4 -> packed bf16x2 hi pair + lo pair
__device__ __forceinline__ void split4(float4 v, uint2& hp, uint2& lp) {
    __nv_bfloat16 h0 = __float2bfloat16_rn(v.x);
    __nv_bfloat16 h1 = __float2bfloat16_rn(v.y);
    __nv_bfloat16 h2 = __float2bfloat16_rn(v.z);
    __nv_bfloat16 h3 = __float2bfloat16_rn(v.w);
    __nv_bfloat16 l0 = __float2bfloat16_rn(v.x - __bfloat162float(h0));
    __nv_bfloat16 l1 = __float2bfloat16_rn(v.y - __bfloat162float(h1));
    __nv_bfloat16 l2 = __float2bfloat16_rn(v.z - __bfloat162float(h2));
    __nv_bfloat16 l3 = __float2bfloat16_rn(v.w - __bfloat162float(h3));
    hp = make_uint2(pack_bf16(h0, h1), pack_bf16(h2, h3));
    lp = make_uint2(pack_bf16(l0, l1), pack_bf16(l2, l3));
}

// ======================= Prologue: scale + transpose + split weights =======================
__global__ void convert_weights_kernel(const float* __restrict__ w) {
    int idx = blockIdx.x * blockDim.x + threadIdx.x;
    if (idx >= KDIM * NOUT) return;
    int k = idx >> 8;          // weight is [K=128][N=256] row-major
    int n = idx & 255;
    float v = w[idx] * LOG2E;  // log2-domain softmax
    __nv_bfloat16 h = __float2bfloat16_rn(v);
    float r = v - __bfloat162float(h);
    __nv_bfloat16 l = __float2bfloat16_rn(r);
    g_whi[n * KDIM + k] = h;
    g_wlo[n * KDIM + k] = l;
}

// ======================= Main fused persistent kernel =======================
// 256 threads = 2 independent groups of 128 (4 warps each) in anti-phase.
// Group warp layout: 1(M) x 4(N); warp tile m32 x n64.
// Accum: 2 m-frags x 8 n8-blocks x 4 regs = 64 fp32 regs/thread.
__global__ void __launch_bounds__(256, 1) density_main_kernel(
    const float* __restrict__ t_in,
    const float* __restrict__ x_in,
    const float* __restrict__ bias_in,
    float* __restrict__ out,
    int n_rows)
{
    extern __shared__ char smem[];
    const int tid  = threadIdx.x;
    const int gid  = tid >> 7;          // group 0 / 1
    const int tg   = tid & 127;         // thread-in-group
    const int lane = tid & 31;
    const int wn   = tg >> 5;           // warp-in-group: 4 warps across N
    const int g    = lane >> 2;         // row within m8 group
    const int cq   = lane & 3;          // col quad
    const int barid = 1 + gid;          // named barrier per group

    const uint32_t smem_u = smem_to_u32(smem);
    float* sbias = reinterpret_cast<float*>(smem + SM_BIAS);
    float* st    = reinterpret_cast<float*>(smem + SM_T)    + gid * 32;
    float* spmax = reinterpret_cast<float*>(smem + SM_PMAX) + gid * 128;
    float* spsum = reinterpret_cast<float*>(smem + SM_PSUM) + gid * 128;
    float* spy   = reinterpret_cast<float*>(smem + SM_PY)   + gid * 128;
    char*  aBuf  = smem + SM_A + gid * A_BUF;

    // ---- load B tiles (weights hi/lo) once; persist across all tiles ----
    {
        const uint4* wh4 = reinterpret_cast<const uint4*>(g_whi);
        const uint4* wl4 = reinterpret_cast<const uint4*>(g_wlo);
        #pragma unroll
        for (int it = 0; it < 16; it++) {           // 256*16 uint4 / 256 thr
            int u = tid + it * 256;
            int n = u >> 4, k8 = u & 15;
            uint32_t off = (uint32_t)n * ROW_BYTES + (uint32_t)k8 * 16;
            *reinterpret_cast<uint4*>(smem + SM_BHI + off) = wh4[u];
            *reinterpret_cast<uint4*>(smem + SM_BLO + off) = wl4[u];
        }
        sbias[tid] = bias_in[tid] * LOG2E;          // log2-domain
    }

    // per-thread invariant ldmatrix address components
    const uint32_t aOff = (uint32_t)(lane & 15) * ROW_BYTES
                        + ((uint32_t)(lane >> 4) << 4);
    const uint32_t bOff = (uint32_t)(64 * wn + (((lane >> 4) << 3) + (lane & 7))) * ROW_BYTES
                        + (((uint32_t)(lane >> 3) & 1u) << 4);

    __syncthreads();

    const int ntiles = n_rows >> 5;                 // 32-row tiles
    const int stride = gridDim.x * 2;
    const int tile0  = blockIdx.x * 2 + gid;

    // ---- preload first tile's x into registers ----
    float4 xr[8];
    if (tile0 < ntiles) {
        const float4* x4 = reinterpret_cast<const float4*>(
            x_in + (size_t)tile0 * (M_TILE * KDIM));
        #pragma unroll
        for (int it = 0; it < 8; it++) xr[it] = x4[tg + it * 128];
    }

    bool first = true;
    for (int tile = tile0; tile < ntiles; tile += stride) {
        const size_t row0 = (size_t)tile << 5;
        const int nxt = tile + stride;
        const bool has_nxt = (nxt < ntiles);

        // ---- store current tile regs -> A smem (convert to bf16 hi/lo) ----
        #pragma unroll
        for (int it = 0; it < 8; it++) {
            int u = tg + it * 128;
            int m = u >> 5, k4 = u & 31;            // 32 float4 per row
            uint2 hp, lp;
            split4(xr[it], hp, lp);
            uint32_t off = (uint32_t)m * ROW_BYTES + (uint32_t)k4 * 8;
            *reinterpret_cast<uint2*>(aBuf + off) = hp;
            *reinterpret_cast<uint2*>(aBuf + A_BUF_HALF + off) = lp;
        }
        if (tg < 32) st[tg] = t_in[row0 + tg];

        asm volatile("bar.sync %0, 128;" :: "r"(barid) : "memory");  // A+t ready

        // ---- one-time anti-phase stagger: group 1 waits for group 0's 1st MMA ----
        if (first && gid == 1) {
            asm volatile("bar.sync 3, 256;" ::: "memory");
        }

        // ---- prefetch next tile's x into registers (hides DRAM under MMA) ----
        if (has_nxt) {
            const float4* x4 = reinterpret_cast<const float4*>(
                x_in + (size_t)nxt * (M_TILE * KDIM));
            #pragma unroll
            for (int it = 0; it < 8; it++) xr[it] = x4[tg + it * 128];
        }

        // ---- MMA mainloop ----
        const uint32_t aBase = smem_u + (uint32_t)(SM_A + gid * A_BUF);
        float d[64];
        #pragma unroll
        for (int i = 0; i < 64; i++) d[i] = 0.0f;

        #pragma unroll 1
        for (int s = 0; s < 8; s++) {
            uint32_t ah[2][4], al[2][4];
            #pragma unroll
            for (int mi = 0; mi < 2; mi++) {
                uint32_t ao = aBase + aOff + (uint32_t)mi * (16 * ROW_BYTES)
                            + (uint32_t)s * 32;
                ldsm_x4(ah[mi], ao);
                ldsm_x4(al[mi], ao + A_BUF_HALF);
            }
            #pragma unroll
            for (int p = 0; p < 4; p++) {
                uint32_t bh[4], bl[4];
                uint32_t bo = bOff + (uint32_t)p * (16 * ROW_BYTES) + (uint32_t)s * 32;
                ldsm_x4(bh, smem_u + SM_BHI + bo);
                ldsm_x4(bl, smem_u + SM_BLO + bo);
                #pragma unroll
                for (int mi = 0; mi < 2; mi++) {
                    float* d0 = d + (mi * 8 + 2 * p) * 4;
                    float* d1 = d + (mi * 8 + 2 * p + 1) * 4;
                    mma_bf16(d0, ah[mi], bh[0], bh[1]);
                    mma_bf16(d0, ah[mi], bl[0], bl[1]);
                    mma_bf16(d0, al[mi], bh[0], bh[1]);
                    mma_bf16(d1, ah[mi], bh[2], bh[3]);
                    mma_bf16(d1, ah[mi], bl[2], bl[3]);
                    mma_bf16(d1, al[mi], bh[2], bh[3]);
                }
            }
        }

        // ---- group 0 signals its first MMA is done (non-blocking) ----
        if (first && gid == 0) {
            asm volatile("bar.arrive 3, 256;" ::: "memory");
        }
        first = false;

        // ---- epilogue phase 1: bias add + per-warp partial row max ----
        #pragma unroll
        for (int mi = 0; mi < 2; mi++) {
            const float NEG_INF = __int_as_float(0xff800000);
            float mlo = NEG_INF, mhi = NEG_INF;
            #pragma unroll
            for (int nj = 0; nj < 8; nj++) {
                int c0 = 64 * wn + 8 * nj + 2 * cq;
                float b0 = sbias[c0], b1 = sbias[c0 + 1];
                int idx = (mi * 8 + nj) * 4;
                d[idx + 0] += b0; d[idx + 1] += b1;
                d[idx + 2] += b0; d[idx + 3] += b1;
                mlo = fmaxf(mlo, fmaxf(d[idx + 0], d[idx + 1]));
                mhi = fmaxf(mhi, fmaxf(d[idx + 2], d[idx + 3]));
            }
            mlo = fmaxf(mlo, __shfl_xor_sync(0xffffffffu, mlo, 1));
            mlo = fmaxf(mlo, __shfl_xor_sync(0xffffffffu, mlo, 2));
            mhi = fmaxf(mhi, __shfl_xor_sync(0xffffffffu, mhi, 1));
            mhi = fmaxf(mhi, __shfl_xor_sync(0xffffffffu, mhi, 2));
            if (cq == 0) {
                int rlo = 16 * mi + g;
                spmax[rlo * 4 + wn]       = mlo;
                spmax[(rlo + 8) * 4 + wn] = mhi;
            }
        }
        asm volatile("bar.sync %0, 128;" :: "r"(barid) : "memory");  // pmax ready

        // ---- epilogue phase 2: ex2 + partial sums + partial gather-numerator ----
        #pragma unroll
        for (int mi = 0; mi < 2; mi++) {
            const int rlo = 16 * mi + g;
            const int rhi = rlo + 8;
            float4 m4a = *reinterpret_cast<const float4*>(spmax + rlo * 4);
            float4 m4b = *reinterpret_cast<const float4*>(spmax + rhi * 4);
            float mlo = fmaxf(fmaxf(m4a.x, m4a.y), fmaxf(m4a.z, m4a.w));
            float mhi = fmaxf(fmaxf(m4b.x, m4b.y), fmaxf(m4b.z, m4b.w));

            float ta = st[rlo], tb = st[rhi];
            float ga = ta * (float)NUM_GRID, gb = tb * (float)NUM_GRID;
            float Ufa = ceilf(ga), Ufb = ceilf(gb);
            float wUa = 1.0f - (Ufa - ga), wUb = 1.0f - (Ufb - gb);
            float wLa = 1.0f - wUa,        wLb = 1.0f - wUb;
            int Uia = (int)Ufa, Uib = (int)Ufb;
            int La  = Uia - 1,  Lb  = Uib - 1;   // -1 at t=0: weight 0, never matches

            float slo = 0.0f, shi = 0.0f, ylo = 0.0f, yhi = 0.0f;
            #pragma unroll
            for (int nj = 0; nj < 8; nj++) {
                int idx = (mi * 8 + nj) * 4;
                int c0 = 64 * wn + 8 * nj + 2 * cq;
                float e0 = ex2f(d[idx + 0] - mlo);
                float e1 = ex2f(d[idx + 1] - mlo);
                float e2 = ex2f(d[idx + 2] - mhi);
                float e3 = ex2f(d[idx + 3] - mhi);
                slo += e0 + e1;
                shi += e2 + e3;
                ylo += ((c0 == La) ? wLa : (c0 == Uia) ? wUa : 0.0f) * e0;
                ylo += ((c0 + 1 == La) ? wLa : (c0 + 1 == Uia) ? wUa : 0.0f) * e1;
                yhi += ((c0 == Lb) ? wLb : (c0 == Uib) ? wUb : 0.0f) * e2;
                yhi += ((c0 + 1 == Lb) ? wLb : (c0 + 1 == Uib) ? wUb : 0.0f) * e3;
            }
            slo += __shfl_xor_sync(0xffffffffu, slo, 1);
            slo += __shfl_xor_sync(0xffffffffu, slo, 2);
            shi += __shfl_xor_sync(0xffffffffu, shi, 1);
            shi += __shfl_xor_sync(0xffffffffu, shi, 2);
            ylo += __shfl_xor_sync(0xffffffffu, ylo, 1);
            ylo += __shfl_xor_sync(0xffffffffu, ylo, 2);
            yhi += __shfl_xor_sync(0xffffffffu, yhi, 1);
            yhi += __shfl_xor_sync(0xffffffffu, yhi, 2);
            if (cq == 0) {
                spsum[rlo * 4 + wn] = slo;
                spsum[rhi * 4 + wn] = shi;
                spy[rlo * 4 + wn]   = ylo;
                spy[rhi * 4 + wn]   = yhi;
            }
        }
        asm volatile("bar.sync %0, 128;" :: "r"(barid) : "memory");  // psum/py ready

        // ---- epilogue phase 3: combine 4 partials per row, write out ----
        if (tg < 32) {
            float4 s4 = *reinterpret_cast<const float4*>(spsum + tg * 4);
            float4 y4 = *reinterpret_cast<const float4*>(spy + tg * 4);
            float ssum = (s4.x + s4.y) + (s4.z + s4.w);
            float ysum = (y4.x + y4.y) + (y4.z + y4.w);
            out[row0 + tg] = ysum / ssum;
        }
        // Next iteration's A/t stores conflict only with this iteration's MMA
        // reads / p2 reads, both ordered behind the two group barriers above.
    }
}

// ======================= Launch =======================
extern "C" void kernel_launch(void* const* d_in, const int* in_sizes, int n_in,
                              void* d_out, int out_size) {
    const float* t_in = (const float*)d_in[0];
    const float* x_in = (const float*)d_in[1];
    const float* w_in = (const float*)d_in[2];
    const float* b_in = (const float*)d_in[3];
    float* out = (float*)d_out;

    int n_rows = in_sizes[0];   // 524288

    cudaFuncSetAttribute(density_main_kernel,
                         cudaFuncAttributeMaxDynamicSharedMemorySize, SM_TOTAL);

    convert_weights_kernel<<<(KDIM * NOUT + 255) / 256, 256>>>(w_in);

    int sms = 0;
    cudaDeviceGetAttribute(&sms, cudaDevAttrMultiProcessorCount, 0);
    if (sms <= 0) sms = 148;
    density_main_kernel<<<sms, 256, SM_TOTAL>>>(t_in, x_in, b_in, out, n_rows);
}

// round 12
// speedup vs baseline: 1.0037x; 1.0037x over previous
#include <cuda_runtime.h>
#include <cuda_bf16.h>
#include <cstdint>
#include <math.h>

// ======================= Problem constants =======================
static constexpr int KDIM     = 128;   // inner dim
static constexpr int NOUT     = 256;   // grid points + 1
static constexpr int NUM_GRID = 255;
static constexpr int M_TILE   = 32;    // rows per group-tile

// Padded smem row stride: 128 bf16 + 8 pad = 272 bytes -> conflict-free ldmatrix
static constexpr int ROW_BYTES = 272;
static constexpr int A_BUF_HALF = M_TILE * ROW_BYTES;       // 8704 (hi or lo)
static constexpr int A_BUF      = 2 * A_BUF_HALF;           // 17408 per group

// SMEM layout (byte offsets in dynamic smem)
static constexpr int SM_BHI  = 0;                           // 256 x 272 = 69632
static constexpr int SM_BLO  = SM_BHI + NOUT * ROW_BYTES;   // 69632
static constexpr int SM_A    = SM_BLO + NOUT * ROW_BYTES;   // 139264: 2 group bufs
static constexpr int SM_BIAS = SM_A + 2 * A_BUF;            // 174080, 256 fp32
static constexpr int SM_T    = SM_BIAS + NOUT * 4;          // 175104, 2x32 fp32
static constexpr int SM_PMAX = SM_T + 256;                  // 175360, 2x32x4 fp32
static constexpr int SM_PSUM = SM_PMAX + 1024;              // 176384
static constexpr int SM_PY   = SM_PSUM + 1024;              // 177408
static constexpr int SM_TOTAL = SM_PY + 1024;               // 178432 (< 227 KB)

static constexpr float LOG2E = 1.4426950408889634f;

// Pre-split weights in gmem, K-major [n][k], bf16 hi/lo (pre-scaled by log2e)
__device__ __align__(16) __nv_bfloat16 g_whi[NOUT * KDIM];
__device__ __align__(16) __nv_bfloat16 g_wlo[NOUT * KDIM];

// ======================= small helpers =======================
__device__ __forceinline__ uint32_t smem_to_u32(const void* p) {
    uint32_t a;
    asm("{ .reg .u64 t; cvta.to.shared.u64 t, %1; cvt.u32.u64 %0, t; }"
        : "=r"(a) : "l"(p));
    return a;
}

__device__ __forceinline__ void ldsm_x4(uint32_t (&r)[4], uint32_t addr) {
    asm volatile("ldmatrix.sync.aligned.m8n8.x4.shared.b16 {%0,%1,%2,%3}, [%4];"
        : "=r"(r[0]), "=r"(r[1]), "=r"(r[2]), "=r"(r[3]) : "r"(addr));
}

__device__ __forceinline__ void mma_bf16(float* d, const uint32_t (&a)[4],
                                         uint32_t b0, uint32_t b1) {
    asm volatile(
        "mma.sync.aligned.m16n8k16.row.col.f32.bf16.bf16.f32 "
        "{%0,%1,%2,%3},{%4,%5,%6,%7},{%8,%9},{%0,%1,%2,%3};"
        : "+f"(d[0]), "+f"(d[1]), "+f"(d[2]), "+f"(d[3])
        : "r"(a[0]), "r"(a[1]), "r"(a[2]), "r"(a[3]), "r"(b0), "r"(b1));
}

__device__ __forceinline__ uint32_t pack_bf16(__nv_bfloat16 a, __nv_bfloat16 b) {
    return (uint32_t)__bfloat16_as_ushort(a) | ((uint32_t)__bfloat16_as_ushort(b) << 16);
}

__device__ __forceinline__ float ex2f(float x) {
    float y;
    asm("ex2.approx.ftz.f32 %0, %1;" : "=f"(y) : "f"(x));
    return y;
}

// convert one float4 -> packed bf16x2 hi pair + lo pair
__device__ __forceinline__ void split4(float4 v, uint2& hp, uint2& lp) {
    __nv_bfloat16 h0 = __float2bfloat16_rn(v.x);
    __nv_bfloat16 h1 = __float2bfloat16_rn(v.y);
    __nv_bfloat16 h2 = __float2bfloat16_rn(v.z);
    __nv_bfloat16 h3 = __float2bfloat16_rn(v.w);
    __nv_bfloat16 l0 = __float2bfloat16_rn(v.x - __bfloat162float(h0));
    __nv_bfloat16 l1 = __float2bfloat16_rn(v.y - __bfloat162float(h1));
    __nv_bfloat16 l2 = __float2bfloat16_rn(v.z - __bfloat162float(h2));
    __nv_bfloat16 l3 = __float2bfloat16_rn(v.w - __bfloat162float(h3));
    hp = make_uint2(pack_bf16(h0, h1), pack_bf16(h2, h3));
    lp = make_uint2(pack_bf16(l0, l1), pack_bf16(l2, l3));
}

// ======================= Prologue: scale + transpose + split weights =======================
__global__ void convert_weights_kernel(const float* __restrict__ w) {
    int idx = blockIdx.x * blockDim.x + threadIdx.x;
    if (idx >= KDIM * NOUT) return;
    int k = idx >> 8;          // weight is [K=128][N=256] row-major
    int n = idx & 255;
    float v = w[idx] * LOG2E;  // log2-domain softmax
    __nv_bfloat16 h = __float2bfloat16_rn(v);
    float r = v - __bfloat162float(h);
    __nv_bfloat16 l = __float2bfloat16_rn(r);
    g_whi[n * KDIM + k] = h;
    g_wlo[n * KDIM + k] = l;
}

// ======================= Main fused persistent kernel =======================
// 256 threads = 2 independent groups of 128 (4 warps each) in anti-phase.
// Group warp layout: 1(M) x 4(N); warp tile m32 x n64.
// Accum: 2 m-frags x 8 n8-blocks x 4 regs = 64 fp32 regs/thread.
__global__ void __launch_bounds__(256, 1) density_main_kernel(
    const float* __restrict__ t_in,
    const float* __restrict__ x_in,
    const float* __restrict__ bias_in,
    float* __restrict__ out,
    int n_rows)
{
    extern __shared__ char smem[];
    const int tid  = threadIdx.x;
    const int gid  = tid >> 7;          // group 0 / 1
    const int tg   = tid & 127;         // thread-in-group
    const int lane = tid & 31;
    const int wn   = tg >> 5;           // warp-in-group: 4 warps across N
    const int g    = lane >> 2;         // row within m8 group
    const int cq   = lane & 3;          // col quad
    const int barid = 1 + gid;          // named barrier per group

    const uint32_t smem_u = smem_to_u32(smem);
    float* sbias = reinterpret_cast<float*>(smem + SM_BIAS);
    float* st    = reinterpret_cast<float*>(smem + SM_T)    + gid * 32;
    float* spmax = reinterpret_cast<float*>(smem + SM_PMAX) + gid * 128;
    float* spsum = reinterpret_cast<float*>(smem + SM_PSUM) + gid * 128;
    float* spy   = reinterpret_cast<float*>(smem + SM_PY)   + gid * 128;
    char*  aBuf  = smem + SM_A + gid * A_BUF;

    // ---- load B tiles (weights hi/lo) once; persist across all tiles ----
    {
        const uint4* wh4 = reinterpret_cast<const uint4*>(g_whi);
        const uint4* wl4 = reinterpret_cast<const uint4*>(g_wlo);
        #pragma unroll
        for (int it = 0; it < 16; it++) {           // 256*16 uint4 / 256 thr
            int u = tid + it * 256;
            int n = u >> 4, k8 = u & 15;
            uint32_t off = (uint32_t)n * ROW_BYTES + (uint32_t)k8 * 16;
            *reinterpret_cast<uint4*>(smem + SM_BHI + off) = wh4[u];
            *reinterpret_cast<uint4*>(smem + SM_BLO + off) = wl4[u];
        }
        sbias[tid] = bias_in[tid] * LOG2E;          // log2-domain
    }

    // per-thread invariant ldmatrix address components
    const uint32_t aOff = (uint32_t)(lane & 15) * ROW_BYTES
                        + ((uint32_t)(lane >> 4) << 4);
    const uint32_t bOff = (uint32_t)(64 * wn + (((lane >> 4) << 3) + (lane & 7))) * ROW_BYTES
                        + (((uint32_t)(lane >> 3) & 1u) << 4);

    __syncthreads();

    const int ntiles = n_rows >> 5;                 // 32-row tiles
    const int stride = gridDim.x * 2;
    const int tile0  = blockIdx.x * 2 + gid;

    // ---- preload first tile's x into registers ----
    float4 xr[8];
    if (tile0 < ntiles) {
        const float4* x4 = reinterpret_cast<const float4*>(
            x_in + (size_t)tile0 * (M_TILE * KDIM));
        #pragma unroll
        for (int it = 0; it < 8; it++) xr[it] = x4[tg + it * 128];
    }

    bool first = true;
    for (int tile = tile0; tile < ntiles; tile += stride) {
        const size_t row0 = (size_t)tile << 5;
        const int nxt = tile + stride;
        const bool has_nxt = (nxt < ntiles);

        // ---- store current tile regs -> A smem (convert to bf16 hi/lo) ----
        #pragma unroll
        for (int it = 0; it < 8; it++) {
            int u = tg + it * 128;
            int m = u >> 5, k4 = u & 31;            // 32 float4 per row
            uint2 hp, lp;
            split4(xr[it], hp, lp);
            uint32_t off = (uint32_t)m * ROW_BYTES + (uint32_t)k4 * 8;
            *reinterpret_cast<uint2*>(aBuf + off) = hp;
            *reinterpret_cast<uint2*>(aBuf + A_BUF_HALF + off) = lp;
        }
        if (tg < 32) st[tg] = t_in[row0 + tg];

        asm volatile("bar.sync %0, 128;" :: "r"(barid) : "memory");  // A+t ready

        // ---- one-time anti-phase stagger: group 1 waits for group 0's 1st MMA ----
        if (first && gid == 1) {
            asm volatile("bar.sync 3, 256;" ::: "memory");
        }

        // ---- prefetch next tile's x into registers (hides DRAM under MMA) ----
        if (has_nxt) {
            const float4* x4 = reinterpret_cast<const float4*>(
                x_in + (size_t)nxt * (M_TILE * KDIM));
            #pragma unroll
            for (int it = 0; it < 8; it++) xr[it] = x4[tg + it * 128];
        }

        // ---- MMA mainloop ----
        const uint32_t aBase = smem_u + (uint32_t)(SM_A + gid * A_BUF);
        float d[64];
        #pragma unroll
        for (int i = 0; i < 64; i++) d[i] = 0.0f;

        #pragma unroll 1
        for (int s = 0; s < 8; s++) {
            uint32_t ah[2][4], al[2][4];
            #pragma unroll
            for (int mi = 0; mi < 2; mi++) {
                uint32_t ao = aBase + aOff + (uint32_t)mi * (16 * ROW_BYTES)
                            + (uint32_t)s * 32;
                ldsm_x4(ah[mi], ao);
                ldsm_x4(al[mi], ao + A_BUF_HALF);
            }
            #pragma unroll
            for (int p = 0; p < 4; p++) {
                uint32_t bh[4], bl[4];
                uint32_t bo = bOff + (uint32_t)p * (16 * ROW_BYTES) + (uint32_t)s * 32;
                ldsm_x4(bh, smem_u + SM_BHI + bo);
                ldsm_x4(bl, smem_u + SM_BLO + bo);
                #pragma unroll
                for (int mi = 0; mi < 2; mi++) {
                    float* d0 = d + (mi * 8 + 2 * p) * 4;
                    float* d1 = d + (mi * 8 + 2 * p + 1) * 4;
                    mma_bf16(d0, ah[mi], bh[0], bh[1]);
                    mma_bf16(d0, ah[mi], bl[0], bl[1]);
                    mma_bf16(d0, al[mi], bh[0], bh[1]);
                    mma_bf16(d1, ah[mi], bh[2], bh[3]);
                    mma_bf16(d1, ah[mi], bl[2], bl[3]);
                    mma_bf16(d1, al[mi], bh[2], bh[3]);
                }
            }
        }

        // ---- group 0 signals its first MMA is done (non-blocking) ----
        if (first && gid == 0) {
            asm volatile("bar.arrive 3, 256;" ::: "memory");
        }
        first = false;

        // ---- epilogue phase 1: bias add + per-warp partial row max ----
        #pragma unroll
        for (int mi = 0; mi < 2; mi++) {
            const float NEG_INF = __int_as_float(0xff800000);
            float mlo = NEG_INF, mhi = NEG_INF;
            #pragma unroll
            for (int nj = 0; nj < 8; nj++) {
                int c0 = 64 * wn + 8 * nj + 2 * cq;
                float b0 = sbias[c0], b1 = sbias[c0 + 1];
                int idx = (mi * 8 + nj) * 4;
                d[idx + 0] += b0; d[idx + 1] += b1;
                d[idx + 2] += b0; d[idx + 3] += b1;
                mlo = fmaxf(mlo, fmaxf(d[idx + 0], d[idx + 1]));
                mhi = fmaxf(mhi, fmaxf(d[idx + 2], d[idx + 3]));
            }
            mlo = fmaxf(mlo, __shfl_xor_sync(0xffffffffu, mlo, 1));
            mlo = fmaxf(mlo, __shfl_xor_sync(0xffffffffu, mlo, 2));
            mhi = fmaxf(mhi, __shfl_xor_sync(0xffffffffu, mhi, 1));
            mhi = fmaxf(mhi, __shfl_xor_sync(0xffffffffu, mhi, 2));
            if (cq == 0) {
                int rlo = 16 * mi + g;
                spmax[rlo * 4 + wn]       = mlo;
                spmax[(rlo + 8) * 4 + wn] = mhi;
            }
        }
        asm volatile("bar.sync %0, 128;" :: "r"(barid) : "memory");  // pmax ready

        // ---- epilogue phase 2: ex2 + partial sums + partial gather-numerator ----
        #pragma unroll
        for (int mi = 0; mi < 2; mi++) {
            const int rlo = 16 * mi + g;
            const int rhi = rlo + 8;
            float4 m4a = *reinterpret_cast<const float4*>(spmax + rlo * 4);
            float4 m4b = *reinterpret_cast<const float4*>(spmax + rhi * 4);
            float mlo = fmaxf(fmaxf(m4a.x, m4a.y), fmaxf(m4a.z, m4a.w));
            float mhi = fmaxf(fmaxf(m4b.x, m4b.y), fmaxf(m4b.z, m4b.w));

            float ta = st[rlo], tb = st[rhi];
            float ga = ta * (float)NUM_GRID, gb = tb * (float)NUM_GRID;
            float Ufa = ceilf(ga), Ufb = ceilf(gb);
            float wUa = 1.0f - (Ufa - ga), wUb = 1.0f - (Ufb - gb);
            float wLa = 1.0f - wUa,        wLb = 1.0f - wUb;
            int Uia = (int)Ufa, Uib = (int)Ufb;
            int La  = Uia - 1,  Lb  = Uib - 1;   // -1 at t=0: weight 0, never matches

            float slo = 0.0f, shi = 0.0f, ylo = 0.0f, yhi = 0.0f;
            #pragma unroll
            for (int nj = 0; nj < 8; nj++) {
                int idx = (mi * 8 + nj) * 4;
                int c0 = 64 * wn + 8 * nj + 2 * cq;
                float e0 = ex2f(d[idx + 0] - mlo);
                float e1 = ex2f(d[idx + 1] - mlo);
                float e2 = ex2f(d[idx + 2] - mhi);
                float e3 = ex2f(d[idx + 3] - mhi);
                slo += e0 + e1;
                shi += e2 + e3;
                ylo += ((c0 == La) ? wLa : (c0 == Uia) ? wUa : 0.0f) * e0;
                ylo += ((c0 + 1 == La) ? wLa : (c0 + 1 == Uia) ? wUa : 0.0f) * e1;
                yhi += ((c0 == Lb) ? wLb : (c0 == Uib) ? wUb : 0.0f) * e2;
                yhi += ((c0 + 1 == Lb) ? wLb : (c0 + 1 == Uib) ? wUb : 0.0f) * e3;
            }
            slo += __shfl_xor_sync(0xffffffffu, slo, 1);
            slo += __shfl_xor_sync(0xffffffffu, slo, 2);
            shi += __shfl_xor_sync(0xffffffffu, shi, 1);
            shi += __shfl_xor_sync(0xffffffffu, shi, 2);
            ylo += __shfl_xor_sync(0xffffffffu, ylo, 1);
            ylo += __shfl_xor_sync(0xffffffffu, ylo, 2);
            yhi += __shfl_xor_sync(0xffffffffu, yhi, 1);
            yhi += __shfl_xor_sync(0xffffffffu, yhi, 2);
            if (cq == 0) {
                spsum[rlo * 4 + wn] = slo;
                spsum[rhi * 4 + wn] = shi;
                spy[rlo * 4 + wn]   = ylo;
                spy[rhi * 4 + wn]   = yhi;
            }
        }
        asm volatile("bar.sync %0, 128;" :: "r"(barid) : "memory");  // psum/py ready

        // ---- epilogue phase 3: combine 4 partials per row, write out ----
        if (tg < 32) {
            float4 s4 = *reinterpret_cast<const float4*>(spsum + tg * 4);
            float4 y4 = *reinterpret_cast<const float4*>(spy + tg * 4);
            float ssum = (s4.x + s4.y) + (s4.z + s4.w);
            float ysum = (y4.x + y4.y) + (y4.z + y4.w);
            out[row0 + tg] = ysum / ssum;
        }
        // Next iteration's A/t stores conflict only with this iteration's MMA
        // reads / p2 reads, both ordered behind the two group barriers above.
    }
}

// ======================= Launch =======================
extern "C" void kernel_launch(void* const* d_in, const int* in_sizes, int n_in,
                              void* d_out, int out_size) {
    const float* t_in = (const float*)d_in[0];
    const float* x_in = (const float*)d_in[1];
    const float* w_in = (const float*)d_in[2];
    const float* b_in = (const float*)d_in[3];
    float* out = (float*)d_out;

    int n_rows = in_sizes[0];   // 524288

    cudaFuncSetAttribute(density_main_kernel,
                         cudaFuncAttributeMaxDynamicSharedMemorySize, SM_TOTAL);

    convert_weights_kernel<<<(KDIM * NOUT + 255) / 256, 256>>>(w_in);

    int sms = 0;
    cudaDeviceGetAttribute(&sms, cudaDevAttrMultiProcessorCount, 0);
    if (sms <= 0) sms = 148;
    density_main_kernel<<<sms, 256, SM_TOTAL>>>(t_in, x_in, b_in, out, n_rows);
}